// round 10
// baseline (speedup 1.0000x reference)
#include <cuda_runtime.h>
#include <cuda_bf16.h>
#include <math.h>

// Problem constants (fixed shapes from reference)
#define TT 512      // tokens
#define DD 1024     // model dim
#define FF 4096     // ffn dim
#define EE 8        // experts
#define RR 16       // lora rank
#define KK 2        // top-k
#define SCALE 2.0f  // lora_alpha / lora_r = 32/16
#define EPSV 1e-6f

// ------------------------------------------------------------------
// Scratch (static __device__) — R2 set + 32KB for expert grouping.
// ------------------------------------------------------------------
__device__ float g_t[TT * DD];
__device__ float g_base[TT * 2 * FF];
__device__ float g_act[TT * KK * FF];
__device__ float g_down[TT * KK * DD];
__device__ float g_c1[TT * KK * RR];
__device__ float g_c3[TT * KK * RR];
__device__ float g_c2[TT * KK * RR];
__device__ int   g_eidx[TT * KK];
__device__ float g_ew[TT * KK];
__device__ int   g_cnt[EE];
__device__ int   g_grp[EE * TT * KK];

// ------------------------------------------------------------------
// K0: zero expert counters
// ------------------------------------------------------------------
__global__ void k_init() {
    if (threadIdx.x < EE) g_cnt[threadIdx.x] = 0;
}

// ------------------------------------------------------------------
// K1: RMSNorm + router (softmax -> top-2 -> renorm) + expert scatter
// grid = TT blocks, 256 threads
// ------------------------------------------------------------------
__global__ __launch_bounds__(256) void k_norm_route(
    const float* __restrict__ x, const float* __restrict__ normw,
    const float* __restrict__ gatew)
{
    const int t = blockIdx.x, tid = threadIdx.x;
    const float* xr = x + (size_t)t * DD;

    float ss = 0.f;
    for (int i = tid; i < DD; i += 256) { float v = xr[i]; ss += v * v; }
    #pragma unroll
    for (int o = 16; o; o >>= 1) ss += __shfl_xor_sync(~0u, ss, o);

    __shared__ float sred[8];
    __shared__ float s_inv;
    if ((tid & 31) == 0) sred[tid >> 5] = ss;
    __syncthreads();
    if (tid == 0) {
        float tot = 0.f;
        #pragma unroll
        for (int i = 0; i < 8; i++) tot += sred[i];
        s_inv = rsqrtf(tot / (float)DD + EPSV);
    }
    __syncthreads();
    const float inv = s_inv;
    for (int i = tid; i < DD; i += 256)
        g_t[(size_t)t * DD + i] = xr[i] * inv * normw[i];
    __syncthreads();

    // router logits: one warp per expert
    const int w = tid >> 5, lane = tid & 31;
    const float* gw = gatew + (size_t)w * DD;
    const float* nx = g_t + (size_t)t * DD;
    float p = 0.f;
    for (int i = lane; i < DD; i += 32) p += nx[i] * gw[i];
    #pragma unroll
    for (int o = 16; o; o >>= 1) p += __shfl_xor_sync(~0u, p, o);

    __shared__ float slog[EE];
    if (lane == 0) slog[w] = p;
    __syncthreads();

    if (tid == 0) {
        float m = slog[0];
        #pragma unroll
        for (int i = 1; i < EE; i++) m = fmaxf(m, slog[i]);
        float ex[EE];
        #pragma unroll
        for (int i = 0; i < EE; i++) ex[i] = expf(slog[i] - m);
        // top-2 (first occurrence on ties, matching lax.top_k)
        int i0 = 0; float b0 = ex[0];
        #pragma unroll
        for (int i = 1; i < EE; i++) if (ex[i] > b0) { b0 = ex[i]; i0 = i; }
        int i1 = -1; float b1v = -1.f;
        #pragma unroll
        for (int i = 0; i < EE; i++)
            if (i != i0 && ex[i] > b1v) { b1v = ex[i]; i1 = i; }
        // softmax denominator cancels under renormalization
        const float s = b0 + b1v;
        g_eidx[t * 2 + 0] = i0;  g_ew[t * 2 + 0] = b0 / s;
        g_eidx[t * 2 + 1] = i1;  g_ew[t * 2 + 1] = b1v / s;
        // scatter slots into per-expert lists
        int p0 = atomicAdd(&g_cnt[i0], 1); g_grp[i0 * (TT * KK) + p0] = t * 2 + 0;
        int p1 = atomicAdd(&g_cnt[i1], 1); g_grp[i1 * (TT * KK) + p1] = t * 2 + 1;
    }
}

// ------------------------------------------------------------------
// K2: Up-proj base GEMM (verbatim from the passing R2 kernel).
// C[t][n] = g_t[t] . W[n]  where W row n is w1[n] (n<F) or w3[n-F].
// 128x128 tile, BK=16, 8x8 per thread, 256 threads. grid = (64, 4)
// ------------------------------------------------------------------
__global__ __launch_bounds__(256) void k_gemm_up(
    const float* __restrict__ w1, const float* __restrict__ w3)
{
    constexpr int BM = 128, BN = 128, BK = 16;
    __shared__ float As[BK][BM + 4];
    __shared__ float Bs[BK][BN + 4];

    const int tid = threadIdx.x;
    const int bm = blockIdx.y * BM;
    const int bn = blockIdx.x * BN;
    const int tx = tid % 16;
    const int ty = tid / 16;

    float acc[8][8];
    #pragma unroll
    for (int i = 0; i < 8; i++)
        #pragma unroll
        for (int j = 0; j < 8; j++) acc[i][j] = 0.f;

    for (int k0 = 0; k0 < DD; k0 += BK) {
        {
            const int r = tid >> 1;
            const int c4 = (tid & 1) * 8;
            const float4 v0 = *reinterpret_cast<const float4*>(
                &g_t[(size_t)(bm + r) * DD + k0 + c4]);
            const float4 v1 = *reinterpret_cast<const float4*>(
                &g_t[(size_t)(bm + r) * DD + k0 + c4 + 4]);
            As[c4 + 0][r] = v0.x; As[c4 + 1][r] = v0.y;
            As[c4 + 2][r] = v0.z; As[c4 + 3][r] = v0.w;
            As[c4 + 4][r] = v1.x; As[c4 + 5][r] = v1.y;
            As[c4 + 6][r] = v1.z; As[c4 + 7][r] = v1.w;
        }
        {
            const int r = tid >> 1;
            const int c4 = (tid & 1) * 8;
            const int n = bn + r;
            const float* Brow = (n < FF) ? (w1 + (size_t)n * DD)
                                         : (w3 + (size_t)(n - FF) * DD);
            const float4 v0 = *reinterpret_cast<const float4*>(&Brow[k0 + c4]);
            const float4 v1 = *reinterpret_cast<const float4*>(&Brow[k0 + c4 + 4]);
            Bs[c4 + 0][r] = v0.x; Bs[c4 + 1][r] = v0.y;
            Bs[c4 + 2][r] = v0.z; Bs[c4 + 3][r] = v0.w;
            Bs[c4 + 4][r] = v1.x; Bs[c4 + 5][r] = v1.y;
            Bs[c4 + 6][r] = v1.z; Bs[c4 + 7][r] = v1.w;
        }
        __syncthreads();

        #pragma unroll
        for (int k = 0; k < BK; k++) {
            float ra[8], rb[8];
            #pragma unroll
            for (int q = 0; q < 2; q++) {
                float4 v = *reinterpret_cast<const float4*>(&As[k][ty * 8 + q * 4]);
                ra[q * 4 + 0] = v.x; ra[q * 4 + 1] = v.y;
                ra[q * 4 + 2] = v.z; ra[q * 4 + 3] = v.w;
            }
            #pragma unroll
            for (int q = 0; q < 2; q++) {
                float4 v = *reinterpret_cast<const float4*>(&Bs[k][tx * 8 + q * 4]);
                rb[q * 4 + 0] = v.x; rb[q * 4 + 1] = v.y;
                rb[q * 4 + 2] = v.z; rb[q * 4 + 3] = v.w;
            }
            #pragma unroll
            for (int i = 0; i < 8; i++)
                #pragma unroll
                for (int j = 0; j < 8; j++)
                    acc[i][j] = fmaf(ra[i], rb[j], acc[i][j]);
        }
        __syncthreads();
    }

    #pragma unroll
    for (int i = 0; i < 8; i++) {
        const size_t row = (size_t)(bm + ty * 8 + i) * (2 * FF) + bn + tx * 8;
        #pragma unroll
        for (int j = 0; j < 8; j += 4) {
            *reinterpret_cast<float4*>(&g_base[row + j]) =
                make_float4(acc[i][j], acc[i][j+1], acc[i][j+2], acc[i][j+3]);
        }
    }
}

// ------------------------------------------------------------------
// K3: up-proj LoRA coefficients (verbatim R2)
// ------------------------------------------------------------------
__global__ __launch_bounds__(256) void k_lora_up_coeff(
    const float* __restrict__ a1, const float* __restrict__ a3)
{
    const int t = blockIdx.x, tid = threadIdx.x;
    const int w = tid >> 5, lane = tid & 31;
    const float* nx = g_t + (size_t)t * DD;

    #pragma unroll
    for (int dj = 0; dj < 8; dj++) {
        const int dIdx = w * 8 + dj;
        const int slot = dIdx >> 5;
        const int mat  = (dIdx >> 4) & 1;
        const int r    = dIdx & 15;
        const int e    = g_eidx[t * 2 + slot];
        const float* ar = (mat ? a3 : a1) + ((size_t)e * RR + r) * DD;
        float p = 0.f;
        for (int i = lane; i < DD; i += 32) p += nx[i] * ar[i];
        #pragma unroll
        for (int o = 16; o; o >>= 1) p += __shfl_xor_sync(~0u, p, o);
        if (lane == 0)
            (mat ? g_c3 : g_c1)[(size_t)(t * 2 + slot) * RR + r] = p;
    }
}

// ------------------------------------------------------------------
// K4: expert-grouped SwiGLU activation (replaces R2's k_act)
// grid = (FF/128, EE), 256 threads
// ------------------------------------------------------------------
__global__ __launch_bounds__(256) void k_act_grouped(
    const float* __restrict__ b1, const float* __restrict__ b3)
{
    const int ft = blockIdx.x, e = blockIdx.y, tid = threadIdx.x;
    const int f0 = ft * 128;

    __shared__ float b1s[RR][128], b3s[RR][128];
    __shared__ float c1s[2][RR], c3s[2][RR];

    for (int i = tid; i < 128 * RR; i += 256) {
        const int f = i >> 4, r = i & 15;
        b1s[r][f] = b1[((size_t)e * FF + f0 + f) * RR + r];
        b3s[r][f] = b3[((size_t)e * FF + f0 + f) * RR + r];
    }
    __syncthreads();

    const int n_e = g_cnt[e];

    for (int i0 = 0; i0 < n_e; i0 += 2) {
        if (tid < 64) {
            const int tok = tid >> 5, q = tid & 31;
            if (i0 + tok < n_e) {
                const int ts = g_grp[e * (TT * KK) + i0 + tok];
                if (q < RR) c1s[tok][q] = g_c1[(size_t)ts * RR + q];
                else        c3s[tok][q - RR] = g_c3[(size_t)ts * RR + (q - RR)];
            }
        }
        __syncthreads();

        const int tok = tid >> 7, f = tid & 127;
        if (i0 + tok < n_e) {
            const int ts = g_grp[e * (TT * KK) + i0 + tok];
            const int t = ts >> 1;
            float d1 = 0.f, d3 = 0.f;
            #pragma unroll
            for (int r = 0; r < RR; r++) {
                d1 += b1s[r][f] * c1s[tok][r];
                d3 += b3s[r][f] * c3s[tok][r];
            }
            const float h1 = g_base[(size_t)t * (2 * FF) + f0 + f] + SCALE * d1;
            const float h3 = g_base[(size_t)t * (2 * FF) + FF + f0 + f] + SCALE * d3;
            const float sig = 1.f / (1.f + expf(-h1));
            g_act[(size_t)ts * FF + f0 + f] = h1 * sig * h3;
        }
        __syncthreads();
    }
}

// ------------------------------------------------------------------
// K5: down-proj LoRA coefficients (verbatim R2)
// ------------------------------------------------------------------
__global__ __launch_bounds__(256) void k_lora_down_coeff(
    const float* __restrict__ a2)
{
    const int ts = blockIdx.x, tid = threadIdx.x;
    const int w = tid >> 5, lane = tid & 31;
    const int e = g_eidx[ts];
    const float* ac = g_act + (size_t)ts * FF;

    #pragma unroll
    for (int jj = 0; jj < 2; jj++) {
        const int r = w * 2 + jj;
        const float* ar = a2 + ((size_t)e * RR + r) * FF;
        float p = 0.f;
        for (int i = lane; i < FF; i += 32) p += ac[i] * ar[i];
        #pragma unroll
        for (int o = 16; o; o >>= 1) p += __shfl_xor_sync(~0u, p, o);
        if (lane == 0) g_c2[(size_t)ts * RR + r] = p;
    }
}

// ------------------------------------------------------------------
// K6: Down-proj base GEMM (verbatim R2).
// 64x64 tile, BK=16, 4x4 per thread, 256 threads. grid = (16, 16)
// ------------------------------------------------------------------
__global__ __launch_bounds__(256) void k_gemm_down(
    const float* __restrict__ w2)
{
    constexpr int BM = 64, BN = 64, BK = 16;
    __shared__ float As[BK][BM + 4];
    __shared__ float Bs[BK][BN + 4];

    const int tid = threadIdx.x;
    const int bm = blockIdx.y * BM;
    const int bn = blockIdx.x * BN;
    const int tx = tid % 16;
    const int ty = tid / 16;

    float acc[4][4];
    #pragma unroll
    for (int i = 0; i < 4; i++)
        #pragma unroll
        for (int j = 0; j < 4; j++) acc[i][j] = 0.f;

    for (int k0 = 0; k0 < FF; k0 += BK) {
        {
            const int r = tid >> 2;
            const int c4 = (tid & 3) * 4;
            const float4 v = *reinterpret_cast<const float4*>(
                &g_act[(size_t)(bm + r) * FF + k0 + c4]);
            As[c4 + 0][r] = v.x; As[c4 + 1][r] = v.y;
            As[c4 + 2][r] = v.z; As[c4 + 3][r] = v.w;
        }
        {
            const int r = tid >> 2;
            const int c4 = (tid & 3) * 4;
            const float4 v = *reinterpret_cast<const float4*>(
                &w2[(size_t)(bn + r) * FF + k0 + c4]);
            Bs[c4 + 0][r] = v.x; Bs[c4 + 1][r] = v.y;
            Bs[c4 + 2][r] = v.z; Bs[c4 + 3][r] = v.w;
        }
        __syncthreads();

        #pragma unroll
        for (int k = 0; k < BK; k++) {
            float ra[4], rb[4];
            {
                float4 v = *reinterpret_cast<const float4*>(&As[k][ty * 4]);
                ra[0] = v.x; ra[1] = v.y; ra[2] = v.z; ra[3] = v.w;
            }
            {
                float4 v = *reinterpret_cast<const float4*>(&Bs[k][tx * 4]);
                rb[0] = v.x; rb[1] = v.y; rb[2] = v.z; rb[3] = v.w;
            }
            #pragma unroll
            for (int i = 0; i < 4; i++)
                #pragma unroll
                for (int j = 0; j < 4; j++)
                    acc[i][j] = fmaf(ra[i], rb[j], acc[i][j]);
        }
        __syncthreads();
    }

    #pragma unroll
    for (int i = 0; i < 4; i++) {
        const size_t row = (size_t)(bm + ty * 4 + i) * DD + bn + tx * 4;
        *reinterpret_cast<float4*>(&g_down[row]) =
            make_float4(acc[i][0], acc[i][1], acc[i][2], acc[i][3]);
    }
}

// ------------------------------------------------------------------
// K7: epilogue — weighted mix of (down base + LoRA down) (verbatim R2)
// ------------------------------------------------------------------
__global__ __launch_bounds__(256) void k_epilogue(
    const float* __restrict__ b2, float* __restrict__ out)
{
    const int t = blockIdx.x, tid = threadIdx.x;

    __shared__ float c2s[KK][RR];
    __shared__ float ws[KK];
    __shared__ int es[KK];
    if (tid < KK * RR) c2s[tid >> 4][tid & 15] =
        g_c2[(size_t)(t * 2 + (tid >> 4)) * RR + (tid & 15)];
    if (tid < KK) { ws[tid] = g_ew[t * 2 + tid]; es[tid] = g_eidx[t * 2 + tid]; }
    __syncthreads();

    for (int d = tid; d < DD; d += 256) {
        float acc = 0.f;
        #pragma unroll
        for (int s = 0; s < KK; s++) {
            const float base = g_down[(size_t)(t * 2 + s) * DD + d];
            const float4* B2 = reinterpret_cast<const float4*>(
                b2 + ((size_t)es[s] * DD + d) * RR);
            float l = 0.f;
            #pragma unroll
            for (int q = 0; q < 4; q++) {
                float4 v = B2[q];
                l += v.x * c2s[s][q * 4] + v.y * c2s[s][q * 4 + 1]
                   + v.z * c2s[s][q * 4 + 2] + v.w * c2s[s][q * 4 + 3];
            }
            acc += ws[s] * (base + SCALE * l);
        }
        out[(size_t)t * DD + d] = acc;
    }
}

// ------------------------------------------------------------------
// Launch — kernel launches only
// ------------------------------------------------------------------
extern "C" void kernel_launch(void* const* d_in, const int* in_sizes, int n_in,
                              void* d_out, int out_size)
{
    const float* x     = (const float*)d_in[0];
    const float* normw = (const float*)d_in[1];
    const float* w1    = (const float*)d_in[2];
    const float* w3    = (const float*)d_in[3];
    const float* w2    = (const float*)d_in[4];
    const float* gatew = (const float*)d_in[5];
    const float* a1    = (const float*)d_in[6];
    const float* b1    = (const float*)d_in[7];
    const float* a3    = (const float*)d_in[8];
    const float* b3    = (const float*)d_in[9];
    const float* a2    = (const float*)d_in[10];
    const float* b2    = (const float*)d_in[11];
    float* out = (float*)d_out;

    k_init<<<1, 32>>>();
    k_norm_route<<<TT, 256>>>(x, normw, gatew);

    // Up-proj base GEMM: [512,1024] @ [8192,1024]^T -> g_base
    k_gemm_up<<<dim3((2 * FF) / 128, TT / 128), 256>>>(w1, w3);

    k_lora_up_coeff<<<TT, 256>>>(a1, a3);
    k_act_grouped<<<dim3(FF / 128, EE), 256>>>(b1, b3);
    k_lora_down_coeff<<<TT * KK, 256>>>(a2);

    // Down-proj base GEMM: [1024,4096] @ w2 rows -> g_down
    k_gemm_down<<<dim3(DD / 64, (TT * KK) / 64), 256>>>(w2);

    k_epilogue<<<TT, 256>>>(b2, out);
}

// round 14
// speedup vs baseline: 1.0256x; 1.0256x over previous
#include <cuda_runtime.h>
#include <cuda_bf16.h>
#include <math.h>
#include <stdint.h>

// Problem constants (fixed shapes from reference)
#define TT 512      // tokens
#define DD 1024     // model dim
#define FF 4096     // ffn dim
#define EE 8        // experts
#define RR 16       // lora rank
#define KK 2        // top-k
#define SCALE 2.0f  // lora_alpha / lora_r = 32/16
#define EPSV 1e-6f

// ------------------------------------------------------------------
// Scratch (static __device__) — identical set to the passing R10 kernel.
// ------------------------------------------------------------------
__device__ float g_t[TT * DD];
__device__ float g_base[TT * 2 * FF];
__device__ float g_act[TT * KK * FF];
__device__ float g_down[TT * KK * DD];
__device__ float g_c1[TT * KK * RR];
__device__ float g_c3[TT * KK * RR];
__device__ float g_c2[TT * KK * RR];
__device__ int   g_eidx[TT * KK];
__device__ float g_ew[TT * KK];
__device__ int   g_cnt[EE];
__device__ int   g_grp[EE * TT * KK];

// ------------------------------------------------------------------
// Packed fp32x2 helpers (PTX ISA 8.6, sm_100 family baseline)
// ------------------------------------------------------------------
__device__ __forceinline__ unsigned long long pack_ff(float x, float y) {
    unsigned long long r;
    asm("mov.b64 %0, {%1, %2};" : "=l"(r) : "f"(x), "f"(y));
    return r;
}
__device__ __forceinline__ void unpack_ff(unsigned long long v, float& x, float& y) {
    asm("mov.b64 {%0, %1}, %2;" : "=f"(x), "=f"(y) : "l"(v));
}
#define FMA2(acc, a, b) \
    asm("fma.rn.f32x2 %0, %1, %2, %0;" : "+l"(acc) : "l"(a), "l"(b))

// ------------------------------------------------------------------
// K0: zero expert counters
// ------------------------------------------------------------------
__global__ void k_init() {
    if (threadIdx.x < EE) g_cnt[threadIdx.x] = 0;
}

// ------------------------------------------------------------------
// K1: RMSNorm + router + expert scatter (verbatim R10)
// ------------------------------------------------------------------
__global__ __launch_bounds__(256) void k_norm_route(
    const float* __restrict__ x, const float* __restrict__ normw,
    const float* __restrict__ gatew)
{
    const int t = blockIdx.x, tid = threadIdx.x;
    const float* xr = x + (size_t)t * DD;

    float ss = 0.f;
    for (int i = tid; i < DD; i += 256) { float v = xr[i]; ss += v * v; }
    #pragma unroll
    for (int o = 16; o; o >>= 1) ss += __shfl_xor_sync(~0u, ss, o);

    __shared__ float sred[8];
    __shared__ float s_inv;
    if ((tid & 31) == 0) sred[tid >> 5] = ss;
    __syncthreads();
    if (tid == 0) {
        float tot = 0.f;
        #pragma unroll
        for (int i = 0; i < 8; i++) tot += sred[i];
        s_inv = rsqrtf(tot / (float)DD + EPSV);
    }
    __syncthreads();
    const float inv = s_inv;
    for (int i = tid; i < DD; i += 256)
        g_t[(size_t)t * DD + i] = xr[i] * inv * normw[i];
    __syncthreads();

    const int w = tid >> 5, lane = tid & 31;
    const float* gw = gatew + (size_t)w * DD;
    const float* nx = g_t + (size_t)t * DD;
    float p = 0.f;
    for (int i = lane; i < DD; i += 32) p += nx[i] * gw[i];
    #pragma unroll
    for (int o = 16; o; o >>= 1) p += __shfl_xor_sync(~0u, p, o);

    __shared__ float slog[EE];
    if (lane == 0) slog[w] = p;
    __syncthreads();

    if (tid == 0) {
        float m = slog[0];
        #pragma unroll
        for (int i = 1; i < EE; i++) m = fmaxf(m, slog[i]);
        float ex[EE];
        #pragma unroll
        for (int i = 0; i < EE; i++) ex[i] = expf(slog[i] - m);
        int i0 = 0; float b0 = ex[0];
        #pragma unroll
        for (int i = 1; i < EE; i++) if (ex[i] > b0) { b0 = ex[i]; i0 = i; }
        int i1 = -1; float b1v = -1.f;
        #pragma unroll
        for (int i = 0; i < EE; i++)
            if (i != i0 && ex[i] > b1v) { b1v = ex[i]; i1 = i; }
        const float s = b0 + b1v;
        g_eidx[t * 2 + 0] = i0;  g_ew[t * 2 + 0] = b0 / s;
        g_eidx[t * 2 + 1] = i1;  g_ew[t * 2 + 1] = b1v / s;
        int p0 = atomicAdd(&g_cnt[i0], 1); g_grp[i0 * (TT * KK) + p0] = t * 2 + 0;
        int p1 = atomicAdd(&g_cnt[i1], 1); g_grp[i1 * (TT * KK) + p1] = t * 2 + 1;
    }
}

// ------------------------------------------------------------------
// K2: Up-proj base GEMM with packed f32x2 FMAs.
// C[t][n] = g_t[t] . W[n]; W row n is w1[n] (n<F) or w3[n-F].
// 128x128 tile, BK=16, 8 rows x 8 cols per thread (cols as 4 f32x2).
// ------------------------------------------------------------------
__global__ __launch_bounds__(256) void k_gemm_up(
    const float* __restrict__ w1, const float* __restrict__ w3)
{
    constexpr int BM = 128, BN = 128, BK = 16;
    __shared__ float As[BK][BM + 4];
    __shared__ float Bs[BK][BN + 4];

    const int tid = threadIdx.x;
    const int bm = blockIdx.y * BM;
    const int bn = blockIdx.x * BN;
    const int tx = tid % 16;
    const int ty = tid / 16;

    unsigned long long acc[8][4];
    #pragma unroll
    for (int i = 0; i < 8; i++)
        #pragma unroll
        for (int j = 0; j < 4; j++) acc[i][j] = pack_ff(0.f, 0.f);

    for (int k0 = 0; k0 < DD; k0 += BK) {
        {
            const int r = tid >> 1;
            const int c4 = (tid & 1) * 8;
            const float4 v0 = *reinterpret_cast<const float4*>(
                &g_t[(size_t)(bm + r) * DD + k0 + c4]);
            const float4 v1 = *reinterpret_cast<const float4*>(
                &g_t[(size_t)(bm + r) * DD + k0 + c4 + 4]);
            As[c4 + 0][r] = v0.x; As[c4 + 1][r] = v0.y;
            As[c4 + 2][r] = v0.z; As[c4 + 3][r] = v0.w;
            As[c4 + 4][r] = v1.x; As[c4 + 5][r] = v1.y;
            As[c4 + 6][r] = v1.z; As[c4 + 7][r] = v1.w;
        }
        {
            const int r = tid >> 1;
            const int c4 = (tid & 1) * 8;
            const int n = bn + r;
            const float* Brow = (n < FF) ? (w1 + (size_t)n * DD)
                                         : (w3 + (size_t)(n - FF) * DD);
            const float4 v0 = *reinterpret_cast<const float4*>(&Brow[k0 + c4]);
            const float4 v1 = *reinterpret_cast<const float4*>(&Brow[k0 + c4 + 4]);
            // store transposed: Bs[k][n] with n contiguous
            Bs[c4 + 0][r] = v0.x; Bs[c4 + 1][r] = v0.y;
            Bs[c4 + 2][r] = v0.z; Bs[c4 + 3][r] = v0.w;
            Bs[c4 + 4][r] = v1.x; Bs[c4 + 5][r] = v1.y;
            Bs[c4 + 6][r] = v1.z; Bs[c4 + 7][r] = v1.w;
        }
        __syncthreads();

        #pragma unroll
        for (int k = 0; k < BK; k++) {
            float ra[8];
            #pragma unroll
            for (int q = 0; q < 2; q++) {
                float4 v = *reinterpret_cast<const float4*>(&As[k][ty * 8 + q * 4]);
                ra[q * 4 + 0] = v.x; ra[q * 4 + 1] = v.y;
                ra[q * 4 + 2] = v.z; ra[q * 4 + 3] = v.w;
            }
            unsigned long long rb[4];
            #pragma unroll
            for (int j = 0; j < 4; j++)
                rb[j] = *reinterpret_cast<const unsigned long long*>(
                    &Bs[k][tx * 8 + j * 2]);
            #pragma unroll
            for (int i = 0; i < 8; i++) {
                const unsigned long long aa = pack_ff(ra[i], ra[i]);
                #pragma unroll
                for (int j = 0; j < 4; j++)
                    FMA2(acc[i][j], aa, rb[j]);
            }
        }
        __syncthreads();
    }

    #pragma unroll
    for (int i = 0; i < 8; i++) {
        const size_t row = (size_t)(bm + ty * 8 + i) * (2 * FF) + bn + tx * 8;
        float c0, c1, c2, c3, c4, c5, c6, c7;
        unpack_ff(acc[i][0], c0, c1); unpack_ff(acc[i][1], c2, c3);
        unpack_ff(acc[i][2], c4, c5); unpack_ff(acc[i][3], c6, c7);
        *reinterpret_cast<float4*>(&g_base[row])     = make_float4(c0, c1, c2, c3);
        *reinterpret_cast<float4*>(&g_base[row + 4]) = make_float4(c4, c5, c6, c7);
    }
}

// ------------------------------------------------------------------
// K3: up-proj LoRA coefficients (verbatim R10)
// ------------------------------------------------------------------
__global__ __launch_bounds__(256) void k_lora_up_coeff(
    const float* __restrict__ a1, const float* __restrict__ a3)
{
    const int t = blockIdx.x, tid = threadIdx.x;
    const int w = tid >> 5, lane = tid & 31;
    const float* nx = g_t + (size_t)t * DD;

    #pragma unroll
    for (int dj = 0; dj < 8; dj++) {
        const int dIdx = w * 8 + dj;
        const int slot = dIdx >> 5;
        const int mat  = (dIdx >> 4) & 1;
        const int r    = dIdx & 15;
        const int e    = g_eidx[t * 2 + slot];
        const float* ar = (mat ? a3 : a1) + ((size_t)e * RR + r) * DD;
        float p = 0.f;
        for (int i = lane; i < DD; i += 32) p += nx[i] * ar[i];
        #pragma unroll
        for (int o = 16; o; o >>= 1) p += __shfl_xor_sync(~0u, p, o);
        if (lane == 0)
            (mat ? g_c3 : g_c1)[(size_t)(t * 2 + slot) * RR + r] = p;
    }
}

// ------------------------------------------------------------------
// K4: expert-grouped SwiGLU activation (verbatim R10)
// ------------------------------------------------------------------
__global__ __launch_bounds__(256) void k_act_grouped(
    const float* __restrict__ b1, const float* __restrict__ b3)
{
    const int ft = blockIdx.x, e = blockIdx.y, tid = threadIdx.x;
    const int f0 = ft * 128;

    __shared__ float b1s[RR][128], b3s[RR][128];
    __shared__ float c1s[2][RR], c3s[2][RR];

    for (int i = tid; i < 128 * RR; i += 256) {
        const int f = i >> 4, r = i & 15;
        b1s[r][f] = b1[((size_t)e * FF + f0 + f) * RR + r];
        b3s[r][f] = b3[((size_t)e * FF + f0 + f) * RR + r];
    }
    __syncthreads();

    const int n_e = g_cnt[e];

    for (int i0 = 0; i0 < n_e; i0 += 2) {
        if (tid < 64) {
            const int tok = tid >> 5, q = tid & 31;
            if (i0 + tok < n_e) {
                const int ts = g_grp[e * (TT * KK) + i0 + tok];
                if (q < RR) c1s[tok][q] = g_c1[(size_t)ts * RR + q];
                else        c3s[tok][q - RR] = g_c3[(size_t)ts * RR + (q - RR)];
            }
        }
        __syncthreads();

        const int tok = tid >> 7, f = tid & 127;
        if (i0 + tok < n_e) {
            const int ts = g_grp[e * (TT * KK) + i0 + tok];
            const int t = ts >> 1;
            float d1 = 0.f, d3 = 0.f;
            #pragma unroll
            for (int r = 0; r < RR; r++) {
                d1 += b1s[r][f] * c1s[tok][r];
                d3 += b3s[r][f] * c3s[tok][r];
            }
            const float h1 = g_base[(size_t)t * (2 * FF) + f0 + f] + SCALE * d1;
            const float h3 = g_base[(size_t)t * (2 * FF) + FF + f0 + f] + SCALE * d3;
            const float sig = 1.f / (1.f + expf(-h1));
            g_act[(size_t)ts * FF + f0 + f] = h1 * sig * h3;
        }
        __syncthreads();
    }
}

// ------------------------------------------------------------------
// K5: down-proj LoRA coefficients (verbatim R10)
// ------------------------------------------------------------------
__global__ __launch_bounds__(256) void k_lora_down_coeff(
    const float* __restrict__ a2)
{
    const int ts = blockIdx.x, tid = threadIdx.x;
    const int w = tid >> 5, lane = tid & 31;
    const int e = g_eidx[ts];
    const float* ac = g_act + (size_t)ts * FF;

    #pragma unroll
    for (int jj = 0; jj < 2; jj++) {
        const int r = w * 2 + jj;
        const float* ar = a2 + ((size_t)e * RR + r) * FF;
        float p = 0.f;
        for (int i = lane; i < FF; i += 32) p += ac[i] * ar[i];
        #pragma unroll
        for (int o = 16; o; o >>= 1) p += __shfl_xor_sync(~0u, p, o);
        if (lane == 0) g_c2[(size_t)ts * RR + r] = p;
    }
}

// ------------------------------------------------------------------
// K6: Down-proj base GEMM with packed f32x2 FMAs.
// 64x64 tile, BK=16, 4 rows x 4 cols per thread (cols as 2 f32x2).
// ------------------------------------------------------------------
__global__ __launch_bounds__(256) void k_gemm_down(
    const float* __restrict__ w2)
{
    constexpr int BM = 64, BN = 64, BK = 16;
    __shared__ float As[BK][BM + 4];
    __shared__ float Bs[BK][BN + 4];

    const int tid = threadIdx.x;
    const int bm = blockIdx.y * BM;
    const int bn = blockIdx.x * BN;
    const int tx = tid % 16;
    const int ty = tid / 16;

    unsigned long long acc[4][2];
    #pragma unroll
    for (int i = 0; i < 4; i++) {
        acc[i][0] = pack_ff(0.f, 0.f);
        acc[i][1] = pack_ff(0.f, 0.f);
    }

    for (int k0 = 0; k0 < FF; k0 += BK) {
        {
            const int r = tid >> 2;
            const int c4 = (tid & 3) * 4;
            const float4 v = *reinterpret_cast<const float4*>(
                &g_act[(size_t)(bm + r) * FF + k0 + c4]);
            As[c4 + 0][r] = v.x; As[c4 + 1][r] = v.y;
            As[c4 + 2][r] = v.z; As[c4 + 3][r] = v.w;
        }
        {
            const int r = tid >> 2;
            const int c4 = (tid & 3) * 4;
            const float4 v = *reinterpret_cast<const float4*>(
                &w2[(size_t)(bn + r) * FF + k0 + c4]);
            Bs[c4 + 0][r] = v.x; Bs[c4 + 1][r] = v.y;
            Bs[c4 + 2][r] = v.z; Bs[c4 + 3][r] = v.w;
        }
        __syncthreads();

        #pragma unroll
        for (int k = 0; k < BK; k++) {
            float ra[4];
            {
                float4 v = *reinterpret_cast<const float4*>(&As[k][ty * 4]);
                ra[0] = v.x; ra[1] = v.y; ra[2] = v.z; ra[3] = v.w;
            }
            unsigned long long rb[2];
            rb[0] = *reinterpret_cast<const unsigned long long*>(&Bs[k][tx * 4]);
            rb[1] = *reinterpret_cast<const unsigned long long*>(&Bs[k][tx * 4 + 2]);
            #pragma unroll
            for (int i = 0; i < 4; i++) {
                const unsigned long long aa = pack_ff(ra[i], ra[i]);
                FMA2(acc[i][0], aa, rb[0]);
                FMA2(acc[i][1], aa, rb[1]);
            }
        }
        __syncthreads();
    }

    #pragma unroll
    for (int i = 0; i < 4; i++) {
        const size_t row = (size_t)(bm + ty * 4 + i) * DD + bn + tx * 4;
        float c0, c1, c2, c3;
        unpack_ff(acc[i][0], c0, c1);
        unpack_ff(acc[i][1], c2, c3);
        *reinterpret_cast<float4*>(&g_down[row]) = make_float4(c0, c1, c2, c3);
    }
}

// ------------------------------------------------------------------
// K7: epilogue — weighted mix of (down base + LoRA down) (verbatim R10)
// ------------------------------------------------------------------
__global__ __launch_bounds__(256) void k_epilogue(
    const float* __restrict__ b2, float* __restrict__ out)
{
    const int t = blockIdx.x, tid = threadIdx.x;

    __shared__ float c2s[KK][RR];
    __shared__ float ws[KK];
    __shared__ int es[KK];
    if (tid < KK * RR) c2s[tid >> 4][tid & 15] =
        g_c2[(size_t)(t * 2 + (tid >> 4)) * RR + (tid & 15)];
    if (tid < KK) { ws[tid] = g_ew[t * 2 + tid]; es[tid] = g_eidx[t * 2 + tid]; }
    __syncthreads();

    for (int d = tid; d < DD; d += 256) {
        float acc = 0.f;
        #pragma unroll
        for (int s = 0; s < KK; s++) {
            const float base = g_down[(size_t)(t * 2 + s) * DD + d];
            const float4* B2 = reinterpret_cast<const float4*>(
                b2 + ((size_t)es[s] * DD + d) * RR);
            float l = 0.f;
            #pragma unroll
            for (int q = 0; q < 4; q++) {
                float4 v = B2[q];
                l += v.x * c2s[s][q * 4] + v.y * c2s[s][q * 4 + 1]
                   + v.z * c2s[s][q * 4 + 2] + v.w * c2s[s][q * 4 + 3];
            }
            acc += ws[s] * (base + SCALE * l);
        }
        out[(size_t)t * DD + d] = acc;
    }
}

// ------------------------------------------------------------------
// Launch — kernel launches only
// ------------------------------------------------------------------
extern "C" void kernel_launch(void* const* d_in, const int* in_sizes, int n_in,
                              void* d_out, int out_size)
{
    const float* x     = (const float*)d_in[0];
    const float* normw = (const float*)d_in[1];
    const float* w1    = (const float*)d_in[2];
    const float* w3    = (const float*)d_in[3];
    const float* w2    = (const float*)d_in[4];
    const float* gatew = (const float*)d_in[5];
    const float* a1    = (const float*)d_in[6];
    const float* b1    = (const float*)d_in[7];
    const float* a3    = (const float*)d_in[8];
    const float* b3    = (const float*)d_in[9];
    const float* a2    = (const float*)d_in[10];
    const float* b2    = (const float*)d_in[11];
    float* out = (float*)d_out;

    k_init<<<1, 32>>>();
    k_norm_route<<<TT, 256>>>(x, normw, gatew);

    // Up-proj base GEMM: [512,1024] @ [8192,1024]^T -> g_base
    k_gemm_up<<<dim3((2 * FF) / 128, TT / 128), 256>>>(w1, w3);

    k_lora_up_coeff<<<TT, 256>>>(a1, a3);
    k_act_grouped<<<dim3(FF / 128, EE), 256>>>(b1, b3);
    k_lora_down_coeff<<<TT * KK, 256>>>(a2);

    // Down-proj base GEMM: [1024,4096] @ w2 rows -> g_down
    k_gemm_down<<<dim3(DD / 64, (TT * KK) / 64), 256>>>(w2);

    k_epilogue<<<TT, 256>>>(b2, out);
}

// round 17
// speedup vs baseline: 1.0903x; 1.0631x over previous
#include <cuda_runtime.h>
#include <cuda_bf16.h>
#include <math.h>
#include <stdint.h>

// Problem constants (fixed shapes from reference)
#define TT 512      // tokens
#define DD 1024     // model dim
#define FF 4096     // ffn dim
#define EE 8        // experts
#define RR 16       // lora rank
#define KK 2        // top-k
#define ERR (EE * RR)          // 128 rows per LoRA A matrix
#define NBT (2 * FF + 2 * ERR) // 8448: up-GEMM output width
#define SCALE 2.0f
#define EPSV 1e-6f

// ------------------------------------------------------------------
// Scratch (static __device__)
// ------------------------------------------------------------------
__device__ float g_t[TT * DD];
__device__ float g_base[TT * NBT];        // 16.5 MB: w1x | w3x | t.a1 | t.a3
__device__ float g_act[TT * KK * FF];
__device__ float g_down[TT * KK * DD];
__device__ float g_c2[TT * KK * RR];
__device__ int   g_eidx[TT * KK];
__device__ float g_ew[TT * KK];
__device__ int   g_cnt[EE];
__device__ int   g_grp[EE * TT * KK];

// ------------------------------------------------------------------
// Packed fp32x2 helpers
// ------------------------------------------------------------------
__device__ __forceinline__ unsigned long long pack_ff(float x, float y) {
    unsigned long long r;
    asm("mov.b64 %0, {%1, %2};" : "=l"(r) : "f"(x), "f"(y));
    return r;
}
__device__ __forceinline__ void unpack_ff(unsigned long long v, float& x, float& y) {
    asm("mov.b64 {%0, %1}, %2;" : "=f"(x), "=f"(y) : "l"(v));
}
#define FMA2(acc, a, b) \
    asm("fma.rn.f32x2 %0, %1, %2, %0;" : "+l"(acc) : "l"(a), "l"(b))

// ------------------------------------------------------------------
// K0: zero expert counters
// ------------------------------------------------------------------
__global__ void k_init() {
    if (threadIdx.x < EE) g_cnt[threadIdx.x] = 0;
}

// ------------------------------------------------------------------
// K1: RMSNorm + router + expert scatter (verbatim passing version)
// ------------------------------------------------------------------
__global__ __launch_bounds__(256) void k_norm_route(
    const float* __restrict__ x, const float* __restrict__ normw,
    const float* __restrict__ gatew)
{
    const int t = blockIdx.x, tid = threadIdx.x;
    const float* xr = x + (size_t)t * DD;

    float ss = 0.f;
    for (int i = tid; i < DD; i += 256) { float v = xr[i]; ss += v * v; }
    #pragma unroll
    for (int o = 16; o; o >>= 1) ss += __shfl_xor_sync(~0u, ss, o);

    __shared__ float sred[8];
    __shared__ float s_inv;
    if ((tid & 31) == 0) sred[tid >> 5] = ss;
    __syncthreads();
    if (tid == 0) {
        float tot = 0.f;
        #pragma unroll
        for (int i = 0; i < 8; i++) tot += sred[i];
        s_inv = rsqrtf(tot / (float)DD + EPSV);
    }
    __syncthreads();
    const float inv = s_inv;
    for (int i = tid; i < DD; i += 256)
        g_t[(size_t)t * DD + i] = xr[i] * inv * normw[i];
    __syncthreads();

    const int w = tid >> 5, lane = tid & 31;
    const float* gw = gatew + (size_t)w * DD;
    const float* nx = g_t + (size_t)t * DD;
    float p = 0.f;
    for (int i = lane; i < DD; i += 32) p += nx[i] * gw[i];
    #pragma unroll
    for (int o = 16; o; o >>= 1) p += __shfl_xor_sync(~0u, p, o);

    __shared__ float slog[EE];
    if (lane == 0) slog[w] = p;
    __syncthreads();

    if (tid == 0) {
        float m = slog[0];
        #pragma unroll
        for (int i = 1; i < EE; i++) m = fmaxf(m, slog[i]);
        float ex[EE];
        #pragma unroll
        for (int i = 0; i < EE; i++) ex[i] = expf(slog[i] - m);
        int i0 = 0; float b0 = ex[0];
        #pragma unroll
        for (int i = 1; i < EE; i++) if (ex[i] > b0) { b0 = ex[i]; i0 = i; }
        int i1 = -1; float b1v = -1.f;
        #pragma unroll
        for (int i = 0; i < EE; i++)
            if (i != i0 && ex[i] > b1v) { b1v = ex[i]; i1 = i; }
        const float s = b0 + b1v;
        g_eidx[t * 2 + 0] = i0;  g_ew[t * 2 + 0] = b0 / s;
        g_eidx[t * 2 + 1] = i1;  g_ew[t * 2 + 1] = b1v / s;
        int p0 = atomicAdd(&g_cnt[i0], 1); g_grp[i0 * (TT * KK) + p0] = t * 2 + 0;
        int p1 = atomicAdd(&g_cnt[i1], 1); g_grp[i1 * (TT * KK) + p1] = t * 2 + 1;
    }
}

// ------------------------------------------------------------------
// K2: Up-proj base GEMM + folded LoRA-A coefficients (f32x2 FMAs).
// C[t][n] = g_t[t] . W[n]
//   n in [0, F)           : w1 rows          -> base1
//   n in [F, 2F)          : w3 rows          -> base3
//   n in [2F, 2F+128)     : a1 rows (e*R+r)  -> c1 coeffs
//   n in [2F+128, 2F+256) : a3 rows          -> c3 coeffs
// 128x128 tile, BK=16, 8x8 per thread. grid = (66, 4)
// ------------------------------------------------------------------
__global__ __launch_bounds__(256) void k_gemm_up(
    const float* __restrict__ w1, const float* __restrict__ w3,
    const float* __restrict__ a1, const float* __restrict__ a3)
{
    constexpr int BM = 128, BN = 128, BK = 16;
    __shared__ float As[BK][BM + 4];
    __shared__ float Bs[BK][BN + 4];

    const int tid = threadIdx.x;
    const int bm = blockIdx.y * BM;
    const int bn = blockIdx.x * BN;
    const int tx = tid % 16;
    const int ty = tid / 16;

    unsigned long long acc[8][4];
    #pragma unroll
    for (int i = 0; i < 8; i++)
        #pragma unroll
        for (int j = 0; j < 4; j++) acc[i][j] = pack_ff(0.f, 0.f);

    for (int k0 = 0; k0 < DD; k0 += BK) {
        {
            const int r = tid >> 1;
            const int c4 = (tid & 1) * 8;
            const float4 v0 = *reinterpret_cast<const float4*>(
                &g_t[(size_t)(bm + r) * DD + k0 + c4]);
            const float4 v1 = *reinterpret_cast<const float4*>(
                &g_t[(size_t)(bm + r) * DD + k0 + c4 + 4]);
            As[c4 + 0][r] = v0.x; As[c4 + 1][r] = v0.y;
            As[c4 + 2][r] = v0.z; As[c4 + 3][r] = v0.w;
            As[c4 + 4][r] = v1.x; As[c4 + 5][r] = v1.y;
            As[c4 + 6][r] = v1.z; As[c4 + 7][r] = v1.w;
        }
        {
            const int r = tid >> 1;
            const int c4 = (tid & 1) * 8;
            const int n = bn + r;
            const float* Brow;
            if (n < FF)                 Brow = w1 + (size_t)n * DD;
            else if (n < 2 * FF)        Brow = w3 + (size_t)(n - FF) * DD;
            else if (n < 2 * FF + ERR)  Brow = a1 + (size_t)(n - 2 * FF) * DD;
            else                        Brow = a3 + (size_t)(n - 2 * FF - ERR) * DD;
            const float4 v0 = *reinterpret_cast<const float4*>(&Brow[k0 + c4]);
            const float4 v1 = *reinterpret_cast<const float4*>(&Brow[k0 + c4 + 4]);
            Bs[c4 + 0][r] = v0.x; Bs[c4 + 1][r] = v0.y;
            Bs[c4 + 2][r] = v0.z; Bs[c4 + 3][r] = v0.w;
            Bs[c4 + 4][r] = v1.x; Bs[c4 + 5][r] = v1.y;
            Bs[c4 + 6][r] = v1.z; Bs[c4 + 7][r] = v1.w;
        }
        __syncthreads();

        #pragma unroll
        for (int k = 0; k < BK; k++) {
            float ra[8];
            #pragma unroll
            for (int q = 0; q < 2; q++) {
                float4 v = *reinterpret_cast<const float4*>(&As[k][ty * 8 + q * 4]);
                ra[q * 4 + 0] = v.x; ra[q * 4 + 1] = v.y;
                ra[q * 4 + 2] = v.z; ra[q * 4 + 3] = v.w;
            }
            unsigned long long rb[4];
            #pragma unroll
            for (int j = 0; j < 4; j++)
                rb[j] = *reinterpret_cast<const unsigned long long*>(
                    &Bs[k][tx * 8 + j * 2]);
            #pragma unroll
            for (int i = 0; i < 8; i++) {
                const unsigned long long aa = pack_ff(ra[i], ra[i]);
                #pragma unroll
                for (int j = 0; j < 4; j++)
                    FMA2(acc[i][j], aa, rb[j]);
            }
        }
        __syncthreads();
    }

    #pragma unroll
    for (int i = 0; i < 8; i++) {
        const size_t row = (size_t)(bm + ty * 8 + i) * NBT + bn + tx * 8;
        float c0, c1, c2, c3, c4, c5, c6, c7;
        unpack_ff(acc[i][0], c0, c1); unpack_ff(acc[i][1], c2, c3);
        unpack_ff(acc[i][2], c4, c5); unpack_ff(acc[i][3], c6, c7);
        *reinterpret_cast<float4*>(&g_base[row])     = make_float4(c0, c1, c2, c3);
        *reinterpret_cast<float4*>(&g_base[row + 4]) = make_float4(c4, c5, c6, c7);
    }
}

// ------------------------------------------------------------------
// K4: expert-grouped SwiGLU activation. Coeffs come from the folded
// columns of g_base: c1(t,e,r) = g_base[t][2F + e*R + r],
//                    c3(t,e,r) = g_base[t][2F + 128 + e*R + r].
// grid = (FF/128, EE), 256 threads
// ------------------------------------------------------------------
__global__ __launch_bounds__(256) void k_act_grouped(
    const float* __restrict__ b1, const float* __restrict__ b3)
{
    const int ft = blockIdx.x, e = blockIdx.y, tid = threadIdx.x;
    const int f0 = ft * 128;

    __shared__ float b1s[RR][128], b3s[RR][128];
    __shared__ float c1s[2][RR], c3s[2][RR];

    for (int i = tid; i < 128 * RR; i += 256) {
        const int f = i >> 4, r = i & 15;
        b1s[r][f] = b1[((size_t)e * FF + f0 + f) * RR + r];
        b3s[r][f] = b3[((size_t)e * FF + f0 + f) * RR + r];
    }
    __syncthreads();

    const int n_e = g_cnt[e];

    for (int i0 = 0; i0 < n_e; i0 += 2) {
        if (tid < 64) {
            const int tok = tid >> 5, q = tid & 31;
            if (i0 + tok < n_e) {
                const int ts = g_grp[e * (TT * KK) + i0 + tok];
                const int t = ts >> 1;
                if (q < RR)
                    c1s[tok][q] = g_base[(size_t)t * NBT + 2 * FF + e * RR + q];
                else
                    c3s[tok][q - RR] = g_base[(size_t)t * NBT + 2 * FF + ERR + e * RR + (q - RR)];
            }
        }
        __syncthreads();

        const int tok = tid >> 7, f = tid & 127;
        if (i0 + tok < n_e) {
            const int ts = g_grp[e * (TT * KK) + i0 + tok];
            const int t = ts >> 1;
            float d1 = 0.f, d3 = 0.f;
            #pragma unroll
            for (int r = 0; r < RR; r++) {
                d1 += b1s[r][f] * c1s[tok][r];
                d3 += b3s[r][f] * c3s[tok][r];
            }
            const float h1 = g_base[(size_t)t * NBT + f0 + f] + SCALE * d1;
            const float h3 = g_base[(size_t)t * NBT + FF + f0 + f] + SCALE * d3;
            const float sig = 1.f / (1.f + expf(-h1));
            g_act[(size_t)ts * FF + f0 + f] = h1 * sig * h3;
        }
        __syncthreads();
    }
}

// ------------------------------------------------------------------
// K5: down-proj LoRA coefficients, reworked: 512 threads (16 warps),
// one warp per r, float4 loads (32 iterations per dot).
// grid = TT*KK blocks
// ------------------------------------------------------------------
__global__ __launch_bounds__(512) void k_lora_down_coeff(
    const float* __restrict__ a2)
{
    const int ts = blockIdx.x, tid = threadIdx.x;
    const int w = tid >> 5, lane = tid & 31;   // w = r (0..15)
    const int e = g_eidx[ts];

    const float4* ac4 = reinterpret_cast<const float4*>(g_act + (size_t)ts * FF);
    const float4* ar4 = reinterpret_cast<const float4*>(a2 + ((size_t)e * RR + w) * FF);

    float p = 0.f;
    #pragma unroll 4
    for (int i = lane; i < FF / 4; i += 32) {
        const float4 a = ac4[i];
        const float4 b = ar4[i];
        p += a.x * b.x + a.y * b.y + a.z * b.z + a.w * b.w;
    }
    #pragma unroll
    for (int o = 16; o; o >>= 1) p += __shfl_xor_sync(~0u, p, o);
    if (lane == 0) g_c2[(size_t)ts * RR + w] = p;
}

// ------------------------------------------------------------------
// K6: Down-proj base GEMM with packed f32x2 FMAs (verbatim R14).
// 64x64 tile, BK=16, 4x4 per thread. grid = (16, 16)
// ------------------------------------------------------------------
__global__ __launch_bounds__(256) void k_gemm_down(
    const float* __restrict__ w2)
{
    constexpr int BM = 64, BN = 64, BK = 16;
    __shared__ float As[BK][BM + 4];
    __shared__ float Bs[BK][BN + 4];

    const int tid = threadIdx.x;
    const int bm = blockIdx.y * BM;
    const int bn = blockIdx.x * BN;
    const int tx = tid % 16;
    const int ty = tid / 16;

    unsigned long long acc[4][2];
    #pragma unroll
    for (int i = 0; i < 4; i++) {
        acc[i][0] = pack_ff(0.f, 0.f);
        acc[i][1] = pack_ff(0.f, 0.f);
    }

    for (int k0 = 0; k0 < FF; k0 += BK) {
        {
            const int r = tid >> 2;
            const int c4 = (tid & 3) * 4;
            const float4 v = *reinterpret_cast<const float4*>(
                &g_act[(size_t)(bm + r) * FF + k0 + c4]);
            As[c4 + 0][r] = v.x; As[c4 + 1][r] = v.y;
            As[c4 + 2][r] = v.z; As[c4 + 3][r] = v.w;
        }
        {
            const int r = tid >> 2;
            const int c4 = (tid & 3) * 4;
            const float4 v = *reinterpret_cast<const float4*>(
                &w2[(size_t)(bn + r) * FF + k0 + c4]);
            Bs[c4 + 0][r] = v.x; Bs[c4 + 1][r] = v.y;
            Bs[c4 + 2][r] = v.z; Bs[c4 + 3][r] = v.w;
        }
        __syncthreads();

        #pragma unroll
        for (int k = 0; k < BK; k++) {
            float ra[4];
            {
                float4 v = *reinterpret_cast<const float4*>(&As[k][ty * 4]);
                ra[0] = v.x; ra[1] = v.y; ra[2] = v.z; ra[3] = v.w;
            }
            unsigned long long rb[2];
            rb[0] = *reinterpret_cast<const unsigned long long*>(&Bs[k][tx * 4]);
            rb[1] = *reinterpret_cast<const unsigned long long*>(&Bs[k][tx * 4 + 2]);
            #pragma unroll
            for (int i = 0; i < 4; i++) {
                const unsigned long long aa = pack_ff(ra[i], ra[i]);
                FMA2(acc[i][0], aa, rb[0]);
                FMA2(acc[i][1], aa, rb[1]);
            }
        }
        __syncthreads();
    }

    #pragma unroll
    for (int i = 0; i < 4; i++) {
        const size_t row = (size_t)(bm + ty * 4 + i) * DD + bn + tx * 4;
        float c0, c1, c2, c3;
        unpack_ff(acc[i][0], c0, c1);
        unpack_ff(acc[i][1], c2, c3);
        *reinterpret_cast<float4*>(&g_down[row]) = make_float4(c0, c1, c2, c3);
    }
}

// ------------------------------------------------------------------
// K7: epilogue — weighted mix (verbatim passing version)
// ------------------------------------------------------------------
__global__ __launch_bounds__(256) void k_epilogue(
    const float* __restrict__ b2, float* __restrict__ out)
{
    const int t = blockIdx.x, tid = threadIdx.x;

    __shared__ float c2s[KK][RR];
    __shared__ float ws[KK];
    __shared__ int es[KK];
    if (tid < KK * RR) c2s[tid >> 4][tid & 15] =
        g_c2[(size_t)(t * 2 + (tid >> 4)) * RR + (tid & 15)];
    if (tid < KK) { ws[tid] = g_ew[t * 2 + tid]; es[tid] = g_eidx[t * 2 + tid]; }
    __syncthreads();

    for (int d = tid; d < DD; d += 256) {
        float acc = 0.f;
        #pragma unroll
        for (int s = 0; s < KK; s++) {
            const float base = g_down[(size_t)(t * 2 + s) * DD + d];
            const float4* B2 = reinterpret_cast<const float4*>(
                b2 + ((size_t)es[s] * DD + d) * RR);
            float l = 0.f;
            #pragma unroll
            for (int q = 0; q < 4; q++) {
                float4 v = B2[q];
                l += v.x * c2s[s][q * 4] + v.y * c2s[s][q * 4 + 1]
                   + v.z * c2s[s][q * 4 + 2] + v.w * c2s[s][q * 4 + 3];
            }
            acc += ws[s] * (base + SCALE * l);
        }
        out[(size_t)t * DD + d] = acc;
    }
}

// ------------------------------------------------------------------
// Launch — kernel launches only
// ------------------------------------------------------------------
extern "C" void kernel_launch(void* const* d_in, const int* in_sizes, int n_in,
                              void* d_out, int out_size)
{
    const float* x     = (const float*)d_in[0];
    const float* normw = (const float*)d_in[1];
    const float* w1    = (const float*)d_in[2];
    const float* w3    = (const float*)d_in[3];
    const float* w2    = (const float*)d_in[4];
    const float* gatew = (const float*)d_in[5];
    const float* a1    = (const float*)d_in[6];
    const float* b1    = (const float*)d_in[7];
    const float* a3    = (const float*)d_in[8];
    const float* b3    = (const float*)d_in[9];
    const float* a2    = (const float*)d_in[10];
    const float* b2    = (const float*)d_in[11];
    float* out = (float*)d_out;

    k_init<<<1, 32>>>();
    k_norm_route<<<TT, 256>>>(x, normw, gatew);

    // Up-proj base GEMM + folded LoRA-A coeffs:
    // [512,1024] @ [8448,1024]^T -> g_base
    k_gemm_up<<<dim3(NBT / 128, TT / 128), 256>>>(w1, w3, a1, a3);

    k_act_grouped<<<dim3(FF / 128, EE), 256>>>(b1, b3);
    k_lora_down_coeff<<<TT * KK, 512>>>(a2);

    // Down-proj base GEMM: [1024,4096] @ w2 rows -> g_down
    k_gemm_down<<<dim3(DD / 64, (TT * KK) / 64), 256>>>(w2);

    k_epilogue<<<TT, 256>>>(b2, out);
}